// round 13
// baseline (speedup 1.0000x reference)
#include <cuda_runtime.h>
#include <cstdint>

#define NEGF (-1e30f)
#define EPSF (1e-7f)
#define LN2F (0.69314718055994531f)

constexpr int Bc = 64;
constexpr int Tc = 1024;
constexpr int Cc = 128;
constexpr int Lc = 256;
constexpr int Sc = 2 * Lc + 1;   // 513
constexpr int BLANKc = Cc - 1;   // 127
constexpr int NT = 128;

__device__ float g_alpha[Bc][Sc];
__device__ float g_gamma[Bc][Sc];

__device__ __forceinline__ float ex2f_(float x){ float r; asm("ex2.approx.ftz.f32 %0, %1;" : "=f"(r) : "f"(x)); return r; }
__device__ __forceinline__ float lg2f_(float x){ float r; asm("lg2.approx.f32 %0, %1;"    : "=f"(r) : "f"(x)); return r; }

__device__ __forceinline__ float lse2f(float a, float b){
    float m = fmaxf(a, b), l = fminf(a, b);
    return m + lg2f_(1.0f + ex2f_(l - m));
}
__device__ __forceinline__ float lse3f(float x, float y, float z){
    float hi = fmaxf(x, y), lo = fminf(x, y);
    float m  = fmaxf(hi, z), t1 = fminf(hi, z);
    float mid = fmaxf(t1, lo), low = fminf(t1, lo);
    return m + lg2f_(1.0f + ex2f_(mid - m) + ex2f_(low - m));
}
__device__ __forceinline__ float lse4f(float a, float b, float c, float d){
    float m = fmaxf(fmaxf(a, b), fmaxf(c, d));
    float s = ex2f_(a - m) + ex2f_(b - m) + ex2f_(c - m) + ex2f_(d - m);
    return m + lg2f_(s);
}
__device__ __forceinline__ float lse5f(float a, float b, float c, float d, float e){
    float m = fmaxf(fmaxf(fmaxf(a, b), fmaxf(c, d)), e);
    float s = ex2f_(a - m) + ex2f_(b - m) + ex2f_(c - m) + ex2f_(d - m) + ex2f_(e - m);
    return m + lg2f_(s);
}

// ======= FUSED 2-step forward block (fast path, all steps active) =======
// alpha''[s] = lse_v( alpha[v] + w(s,v) ) + lp2[e_s], weights from lp1 only (off-chain).
#define FWD_FUSE(J, S1, S2, S3, S4) do {                                                \
    lpS[S3][tid] = lg2f_(pA0 + EPSF);                                                   \
    lpS[S4][tid] = lg2f_(pA1 + EPSF);                                                   \
    pA0 = pB0; pA1 = pB1; pB0 = pC0; pB1 = pC1;                                         \
    pC0 = yp[(size_t)(2*(J)+ 9) * Cc + tid];                                            \
    pC1 = yp[(size_t)(2*(J)+10) * Cc + tid];                                            \
    float4 hB = halo[(J)&1][tid+1];                                                     \
    const float lb1 = lpS[S1][BLANKc], lb2 = lpS[S2][BLANKc];                           \
    const float q1 = lpS[S1][e1], q3 = lpS[S1][e3], q5 = lpS[S1][e5];                   \
    const float r3 = lpS[S2][e3], r5 = lpS[S2][e5];                                     \
    const float w2a = lse2f(q5, lb1);                                                   \
    const float w31 = lse2f(lb1, q3);                                                   \
    const float w10 = lse2f(lb1, q1);                                                   \
    const float w13 = skp5 ? lse3f(q5, lb1, q3) : lb1;                                  \
    const float w11 = skp3 ? lse3f(q3, lb1, q1) : lb1;                                  \
    const float wa03 = skp5 ? q3 : NEGF;                                                \
    const float wh13 = (skp5 && skp3) ? q3 : NEGF;                                      \
    const float wh12 = skp3 ? q3 : NEGF;                                                \
    const float wh21 = skp3 ? q1 : NEGF;                                                \
    const float wh31 = (skp3 && skp1) ? q1 : NEGF;                                      \
    const float wh30 = skp1 ? q1 : NEGF;                                                \
    float G3 = lse5f(A3+q5, A2+w2a, A1+w13, A0+wa03, hB.w+wh13) + r5;                   \
    float G2 = lse4f(A2+lb1, A1+w31, A0+q3, hB.w+wh12) + lb2;                           \
    float G1 = lse5f(A1+q3, A0+w31, hB.w+w11, hB.z+wh21, hB.y+wh31) + r3;               \
    float G0 = lse4f(A0+lb1, hB.w+w10, hB.z+q1, hB.y+wh30) + lb2;                       \
    if (isLast) A4 = lse4f(A4+lb1, A3+w2a, A2+q5, A1+(skp5?q5:NEGF)) + lb2;             \
    A0 = G0; A1 = G1; A2 = G2; A3 = G3;                                                 \
    halo[((J)+1)&1][tid+2] = make_float4(A0, A1, A2, A3);                               \
    __syncthreads();                                                                    \
} while (0)

// ======= FUSED 2-step backward block (fast path) =======
#define BWD_FUSE(J, S1, S2, S3, S4) do {                                                \
    lpS[S3][tid] = lg2f_(pA0 + EPSF);                                                   \
    lpS[S4][tid] = lg2f_(pA1 + EPSF);                                                   \
    pA0 = pB0; pA1 = pB1; pB0 = pC0; pB1 = pC1;                                         \
    pC0 = yp[(size_t)(1015 - 2*(J)) * Cc + tid];                                        \
    pC1 = yp[(size_t)(1014 - 2*(J)) * Cc + tid];                                        \
    float4 hU = halo[(J)&1][tid+1];                                                     \
    if (isLast) hU = make_float4(A2, NEGF, NEGF, NEGF);                                 \
    const float lb1 = lpS[S1][BLANKc], lb2 = lpS[S2][BLANKc];                           \
    const float q1 = lpS[S1][eb1], q3 = lpS[S1][eb3], q5 = lpS[S1][eb5], q7 = lpS[S1][eb7]; \
    const float r1 = lpS[S2][eb1], r3 = lpS[S2][eb3], r5 = lpS[S2][eb5];                \
    const float u1 = lse2f(lb2, r1);                                                    \
    const float u3 = lse2f(lb2, r3);                                                    \
    const float v1 = skbA ? lse3f(r1, lb2, r3) : lb2;                                   \
    const float v3 = skbB ? lse3f(r3, lb2, r5) : lb2;                                   \
    float G0 = lse4f(g0+(lb1+lb2), g1+(q1+u1), g2+(r1+lb1), g3+(skbA?(r1+q3):NEGF));    \
    float G1 = lse5f(g1+(r1+q1), g2+(lb1+u1), g3+(q3+v1),                               \
                     hU.x+(skbA?(r3+lb1):NEGF), hU.y+((skbA&&skbB)?(r3+q5):NEGF));      \
    float G2 = lse4f(g2+(lb1+lb2), g3+(q3+u3), hU.x+(r3+lb1), hU.y+(skbB?(r3+q5):NEGF));\
    float G3 = lse5f(g3+(r3+q3), hU.x+(lb1+u3), hU.y+(q5+v3),                           \
                     hU.z+(skbB?(r5+lb1):NEGF), hU.w+((skbB&&skbC)?(r5+q7):NEGF));      \
    if (isLast) A2 = A2 + lb1 + lb2;                                                    \
    g0 = G0; g1 = G1; g2 = G2; g3 = G3;                                                 \
    halo[((J)+1)&1][tid] = make_float4(g0, g1, g2, g3);                                 \
    __syncthreads();                                                                    \
} while (0)

// ======= R10 unfused bodies (general inLen < T path, verbatim) =======
#define FWD_BODY(J, S1, S2, S3, S4, ACT1, ACT2) do {                                   \
    lpS[S3][tid] = lg2f_(pA0 + EPSF);                                                   \
    lpS[S4][tid] = lg2f_(pA1 + EPSF);                                                   \
    pA0 = pB0; pA1 = pB1; pB0 = pC0; pB1 = pC1;                                         \
    pC0 = yp[(size_t)(2*(J)+ 9) * Cc + tid];                                            \
    pC1 = yp[(size_t)(2*(J)+10) * Cc + tid];                                            \
    float4 hB = halo[(J)&1][tid+1];                                                     \
    const float lb1 = lpS[S1][BLANKc], lb2 = lpS[S2][BLANKc];                           \
    float n1 = lse3f(hB.w, hB.z, skp1 ? hB.y : NEGF) + lpS[S1][e1];                     \
    float n2 = lse2f(A0, hB.w) + lb1;                                                   \
    float n3 = lse3f(A1, A0, skp3 ? hB.w : NEGF) + lpS[S1][e3];                         \
    float n4 = lse2f(A2, A1) + lb1;                                                     \
    float n5 = lse3f(A3, A2, skp5 ? A1 : NEGF) + lpS[S1][e5];                           \
    float n6 = 0.f;                                                                     \
    if (isLast) n6 = (ACT1) ? (lse2f(A4, A3) + lb1) : A4;                               \
    if (!(ACT1)) { n1 = hB.w; n2 = A0; n3 = A1; n4 = A2; n5 = A3; }                     \
    float w0 = lse2f(n2, n1) + lb2;                                                     \
    float w1 = lse3f(n3, n2, skp3 ? n1 : NEGF) + lpS[S2][e3];                           \
    float w2 = lse2f(n4, n3) + lb2;                                                     \
    float w3 = lse3f(n5, n4, skp5 ? n3 : NEGF) + lpS[S2][e5];                           \
    if (ACT2) { A0 = w0; A1 = w1; A2 = w2; A3 = w3; }                                   \
    else      { A0 = n2; A1 = n3; A2 = n4; A3 = n5; }                                   \
    if (isLast) A4 = (ACT2) ? (lse2f(n6, n5) + lb2) : n6;                               \
    halo[((J)+1)&1][tid+2] = make_float4(A0, A1, A2, A3);                               \
    __syncthreads();                                                                    \
} while (0)

#define FWD_FINAL(S, ACT) do {                                                          \
    float4 hB = halo[255 & 1][tid+1];                                                   \
    const float lbf = lpS[S][BLANKc];                                                   \
    float w0 = lse2f(A0, hB.w) + lbf;                                                   \
    float w1 = lse3f(A1, A0, skp3 ? hB.w : NEGF) + lpS[S][e3];                          \
    float w2 = lse2f(A2, A1) + lbf;                                                     \
    float w3 = lse3f(A3, A2, skp5 ? A1 : NEGF) + lpS[S][e5];                            \
    float w4 = 0.f;                                                                     \
    if (isLast) w4 = lse2f(A4, A3) + lbf;                                               \
    if (ACT) { A0 = w0; A1 = w1; A2 = w2; A3 = w3; if (isLast) A4 = w4; }               \
} while (0)

#define BWD_BODY(J, S1, S2, S3, S4, ACT1, ACT2) do {                                    \
    lpS[S3][tid] = lg2f_(pA0 + EPSF);                                                   \
    lpS[S4][tid] = lg2f_(pA1 + EPSF);                                                   \
    pA0 = pB0; pA1 = pB1; pB0 = pC0; pB1 = pC1;                                         \
    pC0 = yp[(size_t)(1015 - 2*(J)) * Cc + tid];                                        \
    pC1 = yp[(size_t)(1014 - 2*(J)) * Cc + tid];                                        \
    float4 hU = halo[(J)&1][tid+1];                                                     \
    if (isLast) hU = make_float4(A2, NEGF, NEGF, NEGF);                                 \
    const float lb1 = lpS[S1][BLANKc], lb2 = lpS[S2][BLANKc];                           \
    float D0 = lb1 + g0;             float D1 = lpS[S1][eb1] + g1;                      \
    float D2 = lb1 + g2;             float D3 = lpS[S1][eb3] + g3;                      \
    float D4 = lb1 + hU.x;           float D5 = lpS[S1][eb5] + hU.y;                    \
    float D6 = lb1 + hU.z;           float D7 = lpS[S1][eb7] + hU.w;                    \
    float n0 = lse2f(D0, D1);                                                           \
    float n1 = lse3f(D1, D2, skbA ? D3 : NEGF);                                         \
    float n2 = lse2f(D2, D3);                                                           \
    float n3 = lse3f(D3, D4, skbB ? D5 : NEGF);                                         \
    float n4 = lse2f(D4, D5);                                                           \
    float n5 = lse3f(D5, D6, skbC ? D7 : NEGF);                                         \
    if (!(ACT1)) { n0 = g0; n1 = g1; n2 = g2; n3 = g3; n4 = hU.x; n5 = hU.y; }          \
    float E0 = lb2 + n0;             float E1 = lpS[S2][eb1] + n1;                      \
    float E2 = lb2 + n2;             float E3 = lpS[S2][eb3] + n3;                      \
    float E4 = lb2 + n4;             float E5 = lpS[S2][eb5] + n5;                      \
    float m0 = lse2f(E0, E1);                                                           \
    float m1 = lse3f(E1, E2, skbA ? E3 : NEGF);                                         \
    float m2 = lse2f(E2, E3);                                                           \
    float m3 = lse3f(E3, E4, skbB ? E5 : NEGF);                                         \
    if (ACT2) { g0 = m0; g1 = m1; g2 = m2; g3 = m3; }                                   \
    else      { g0 = n0; g1 = n1; g2 = n2; g3 = n3; }                                   \
    if (isLast) A2 = (ACT2) ? (lb2 + n4) : n4;                                          \
    halo[((J)+1)&1][tid] = make_float4(g0, g1, g2, g3);                                 \
    __syncthreads();                                                                    \
} while (0)

__global__ __launch_bounds__(NT, 1) void ctc_fb_kernel(
    const int*   __restrict__ y_true,        // (B, L)
    const float* __restrict__ y_pred,        // (B, T, C)
    const int*   __restrict__ input_length,  // (B, 1)
    const int*   __restrict__ label_length)  // (B, 1)
{
    __shared__ float  lpS[4][Cc];
    __shared__ float4 halo[2][NT + 2];

    const bool fwd = (blockIdx.x < Bc);
    const int b    = fwd ? blockIdx.x : (blockIdx.x - Bc);
    const int tid  = threadIdx.x;
    const bool isLast = (tid == NT - 1);
    const float* __restrict__ yp = y_pred + (size_t)b * Tc * Cc;
    const int*   __restrict__ yt = y_true + b * Lc;
    const int inLen  = input_length[b];
    const int labLen = label_length[b];

    if (fwd) {
        const int e1 = yt[max(2 * tid - 1, 0)];
        const int e3 = yt[2 * tid];
        const int e5 = yt[2 * tid + 1];
        const bool skp1 = (tid >= 1) && (e1 != yt[max(2 * tid - 2, 0)]);
        const bool skp3 = (tid >= 1) && (e3 != yt[max(2 * tid - 1, 0)]);
        const bool skp5 = (e5 != e3);

        float A0 = NEGF, A1 = NEGF, A2 = NEGF, A3 = NEGF, A4 = NEGF;
        if (tid == 0) {
            A0 = lg2f_(yp[BLANKc] + EPSF);
            if (labLen > 0) A1 = lg2f_(yp[yt[0]] + EPSF);
        }

        lpS[1][tid] = lg2f_(yp[(size_t)1 * Cc + tid] + EPSF);
        lpS[2][tid] = lg2f_(yp[(size_t)2 * Cc + tid] + EPSF);
        float pA0 = yp[(size_t)3 * Cc + tid], pA1 = yp[(size_t)4 * Cc + tid];
        float pB0 = yp[(size_t)5 * Cc + tid], pB1 = yp[(size_t)6 * Cc + tid];
        float pC0 = yp[(size_t)7 * Cc + tid], pC1 = yp[(size_t)8 * Cc + tid];

        halo[0][tid + 2] = make_float4(A0, A1, A2, A3);
        if (tid == 0) {
            float4 n4 = make_float4(NEGF, NEGF, NEGF, NEGF);
            halo[0][0] = n4; halo[0][1] = n4; halo[1][0] = n4; halo[1][1] = n4;
        }
        __syncthreads();

        if (inLen >= Tc) {
            for (int jj = 0; jj < 127; ++jj) {
                const int j = 2 * jj;
                FWD_FUSE(j,     1, 2, 3, 0);
                FWD_FUSE(j + 1, 3, 0, 1, 2);
            }
            FWD_FUSE(254, 1, 2, 3, 0);
            FWD_FINAL(3, true);
        } else {
            for (int jj = 0; jj < 127; ++jj) {
                const int j = 2 * jj;
                FWD_BODY(j,     1, 2, 3, 0, (2*j+1 < inLen), (2*j+2 < inLen));
                FWD_BODY(j + 1, 3, 0, 1, 2, (2*j+3 < inLen), (2*j+4 < inLen));
            }
            FWD_BODY(254, 1, 2, 3, 0, (509 < inLen), (510 < inLen));
            FWD_FINAL(3, (511 < inLen));
        }

        float* __restrict__ aOut = g_alpha[b];
        const int sbase = 4 * tid;
        aOut[sbase] = A0; aOut[sbase + 1] = A1; aOut[sbase + 2] = A2; aOut[sbase + 3] = A3;
        if (isLast) aOut[512] = A4;

    } else {
        const int eb1 = yt[2 * tid];
        const int eb3 = yt[min(2 * tid + 1, Lc - 1)];
        const int eb5 = yt[min(2 * tid + 2, Lc - 1)];
        const int eb7 = yt[min(2 * tid + 3, Lc - 1)];
        const bool skbA = (eb3 != eb1);
        const bool skbB = (tid <= 126) && (eb5 != eb3);
        const bool skbC = (tid <= 126) && (eb7 != eb5);

        const int se = 2 * labLen;
        const int sbase = 4 * tid;
        float g0 = (sbase     == se || (labLen > 0 && sbase     == se - 1)) ? 0.f : NEGF;
        float g1 = (sbase + 1 == se || (labLen > 0 && sbase + 1 == se - 1)) ? 0.f : NEGF;
        float g2 = (sbase + 2 == se || (labLen > 0 && sbase + 2 == se - 1)) ? 0.f : NEGF;
        float g3 = (sbase + 3 == se || (labLen > 0 && sbase + 3 == se - 1)) ? 0.f : NEGF;
        float A2 = (512 == se) ? 0.f : NEGF;   // gamma[512]

        lpS[3][tid] = lg2f_(yp[(size_t)1023 * Cc + tid] + EPSF);
        lpS[2][tid] = lg2f_(yp[(size_t)1022 * Cc + tid] + EPSF);
        float pA0 = yp[(size_t)1021 * Cc + tid], pA1 = yp[(size_t)1020 * Cc + tid];
        float pB0 = yp[(size_t)1019 * Cc + tid], pB1 = yp[(size_t)1018 * Cc + tid];
        float pC0 = yp[(size_t)1017 * Cc + tid], pC1 = yp[(size_t)1016 * Cc + tid];

        halo[0][tid] = make_float4(g0, g1, g2, g3);
        __syncthreads();

        if (inLen >= Tc) {
            for (int jj = 0; jj < 128; ++jj) {
                const int j = 2 * jj;
                BWD_FUSE(j,     3, 2, 1, 0);
                BWD_FUSE(j + 1, 1, 0, 3, 2);
            }
        } else {
            for (int jj = 0; jj < 128; ++jj) {
                const int j = 2 * jj;
                BWD_BODY(j,     3, 2, 1, 0, (1023-2*j < inLen), (1022-2*j < inLen));
                BWD_BODY(j + 1, 1, 0, 3, 2, (1021-2*j < inLen), (1020-2*j < inLen));
            }
        }

        float* __restrict__ gOut = g_gamma[b];
        gOut[sbase] = g0; gOut[sbase + 1] = g1; gOut[sbase + 2] = g2; gOut[sbase + 3] = g3;
        if (isLast) gOut[512] = A2;
    }
}

__global__ __launch_bounds__(128, 1) void ctc_combine_kernel(float* __restrict__ out)
{
    __shared__ float warpRes[4];
    const int b   = blockIdx.x;
    const int tid = threadIdx.x;
    const float* __restrict__ a = g_alpha[b];
    const float* __restrict__ g = g_gamma[b];

    const int s0 = tid * 4;
    float c0 = a[s0]     + g[s0];
    float c1 = a[s0 + 1] + g[s0 + 1];
    float c2 = a[s0 + 2] + g[s0 + 2];
    float c3 = a[s0 + 3] + g[s0 + 3];
    float local = lse2f(lse2f(c0, c1), lse2f(c2, c3));
    if (tid == 127) local = lse2f(local, a[512] + g[512]);
    #pragma unroll
    for (int off = 16; off > 0; off >>= 1)
        local = lse2f(local, __shfl_xor_sync(0xffffffffu, local, off));
    if ((tid & 31) == 0) warpRes[tid >> 5] = local;
    __syncthreads();
    if (tid == 0) {
        float r = lse2f(lse2f(warpRes[0], warpRes[1]), lse2f(warpRes[2], warpRes[3]));
        out[b] = -LN2F * r;
    }
}

extern "C" void kernel_launch(void* const* d_in, const int* in_sizes, int n_in,
                              void* d_out, int out_size) {
    const int*   y_true       = (const int*)d_in[0];
    const float* y_pred       = (const float*)d_in[1];
    const int*   input_length = (const int*)d_in[2];
    const int*   label_length = (const int*)d_in[3];
    float* out = (float*)d_out;

    ctc_fb_kernel<<<2 * Bc, NT>>>(y_true, y_pred, input_length, label_length);
    ctc_combine_kernel<<<Bc, 128>>>(out);
}

// round 14
// speedup vs baseline: 1.7074x; 1.7074x over previous
#include <cuda_runtime.h>
#include <cstdint>

#define NEGF (-1e30f)
#define EPSF (1e-7f)
#define LN2F (0.69314718055994531f)

constexpr int Bc = 64;
constexpr int Tc = 1024;
constexpr int Cc = 128;
constexpr int Lc = 256;
constexpr int Sc = 2 * Lc + 1;   // 513
constexpr int BLANKc = Cc - 1;   // 127
constexpr int NT = 128;

__device__ float g_alpha[Bc][Sc];
__device__ float g_gamma[Bc][Sc];

__device__ __forceinline__ float ex2f_(float x){ float r; asm("ex2.approx.ftz.f32 %0, %1;" : "=f"(r) : "f"(x)); return r; }
__device__ __forceinline__ float lg2f_(float x){ float r; asm("lg2.approx.f32 %0, %1;"    : "=f"(r) : "f"(x)); return r; }

// lse2: l - m == -|a-b|  (FADD + FMNMX + MUFU(-|d|) ... saves one FMNMX)
__device__ __forceinline__ float lse2f(float a, float b){
    float m = fmaxf(a, b);
    float d = a - b;
    return m + lg2f_(1.0f + ex2f_(-fabsf(d)));
}
// lse3: the two non-max values are fmin(fmax(x,y),z) and fmin(x,y) — order in the
// sum doesn't matter, so the full 6-op sort was 2 ops + 1 chain level too many.
__device__ __forceinline__ float lse3f(float x, float y, float z){
    float hi = fmaxf(x, y), lo = fminf(x, y);
    float m  = fmaxf(hi, z);
    float o1 = fminf(hi, z);
    return m + lg2f_(1.0f + ex2f_(o1 - m) + ex2f_(lo - m));
}

// ---------------- forward 2-step block (states: 4*tid .. 4*tid+3, +512 on last) ----------------
#define FWD_BODY(J, S1, S2, S3, S4, ACT1, ACT2) do {                                   \
    lpS[S3][tid] = lg2f_(pA0 + EPSF);                                                   \
    lpS[S4][tid] = lg2f_(pA1 + EPSF);                                                   \
    pA0 = pB0; pA1 = pB1; pB0 = pC0; pB1 = pC1;                                         \
    pC0 = yp[(size_t)(2*(J)+ 9) * Cc + tid];                                            \
    pC1 = yp[(size_t)(2*(J)+10) * Cc + tid];                                            \
    float4 hB = halo[(J)&1][tid+1];                                                     \
    const float lb1 = lpS[S1][BLANKc], lb2 = lpS[S2][BLANKc];                           \
    float n1 = lse3f(hB.w, hB.z, skp1 ? hB.y : NEGF) + lpS[S1][e1];                     \
    float n2 = lse2f(A0, hB.w) + lb1;                                                   \
    float n3 = lse3f(A1, A0, skp3 ? hB.w : NEGF) + lpS[S1][e3];                         \
    float n4 = lse2f(A2, A1) + lb1;                                                     \
    float n5 = lse3f(A3, A2, skp5 ? A1 : NEGF) + lpS[S1][e5];                           \
    float n6 = 0.f;                                                                     \
    if (isLast) n6 = (ACT1) ? (lse2f(A4, A3) + lb1) : A4;                               \
    if (!(ACT1)) { n1 = hB.w; n2 = A0; n3 = A1; n4 = A2; n5 = A3; }                     \
    float w0 = lse2f(n2, n1) + lb2;                                                     \
    float w1 = lse3f(n3, n2, skp3 ? n1 : NEGF) + lpS[S2][e3];                           \
    float w2 = lse2f(n4, n3) + lb2;                                                     \
    float w3 = lse3f(n5, n4, skp5 ? n3 : NEGF) + lpS[S2][e5];                           \
    if (ACT2) { A0 = w0; A1 = w1; A2 = w2; A3 = w3; }                                   \
    else      { A0 = n2; A1 = n3; A2 = n4; A3 = n5; }                                   \
    if (isLast) A4 = (ACT2) ? (lse2f(n6, n5) + lb2) : n6;                               \
    halo[((J)+1)&1][tid+2] = make_float4(A0, A1, A2, A3);                               \
    __syncthreads();                                                                    \
} while (0)

#define FWD_FINAL(S, ACT) do {                                                          \
    float4 hB = halo[255 & 1][tid+1];                                                   \
    const float lbf = lpS[S][BLANKc];                                                   \
    float w0 = lse2f(A0, hB.w) + lbf;                                                   \
    float w1 = lse3f(A1, A0, skp3 ? hB.w : NEGF) + lpS[S][e3];                          \
    float w2 = lse2f(A2, A1) + lbf;                                                     \
    float w3 = lse3f(A3, A2, skp5 ? A1 : NEGF) + lpS[S][e5];                            \
    float w4 = 0.f;                                                                     \
    if (isLast) w4 = lse2f(A4, A3) + lbf;                                               \
    if (ACT) { A0 = w0; A1 = w1; A2 = w2; A3 = w3; if (isLast) A4 = w4; }               \
} while (0)

// ---------------- backward 2-step block (states: 4*tid .. 4*tid+3, +512 on last) ----------------
#define BWD_BODY(J, S1, S2, S3, S4, ACT1, ACT2) do {                                    \
    lpS[S3][tid] = lg2f_(pA0 + EPSF);                                                   \
    lpS[S4][tid] = lg2f_(pA1 + EPSF);                                                   \
    pA0 = pB0; pA1 = pB1; pB0 = pC0; pB1 = pC1;                                         \
    pC0 = yp[(size_t)(1015 - 2*(J)) * Cc + tid];                                        \
    pC1 = yp[(size_t)(1014 - 2*(J)) * Cc + tid];                                        \
    float4 hU = halo[(J)&1][tid+1];                                                     \
    if (isLast) hU = make_float4(A2, NEGF, NEGF, NEGF);                                 \
    const float lb1 = lpS[S1][BLANKc], lb2 = lpS[S2][BLANKc];                           \
    float D0 = lb1 + g0;             float D1 = lpS[S1][eb1] + g1;                      \
    float D2 = lb1 + g2;             float D3 = lpS[S1][eb3] + g3;                      \
    float D4 = lb1 + hU.x;           float D5 = lpS[S1][eb5] + hU.y;                    \
    float D6 = lb1 + hU.z;           float D7 = lpS[S1][eb7] + hU.w;                    \
    float n0 = lse2f(D0, D1);                                                           \
    float n1 = lse3f(D1, D2, skbA ? D3 : NEGF);                                         \
    float n2 = lse2f(D2, D3);                                                           \
    float n3 = lse3f(D3, D4, skbB ? D5 : NEGF);                                         \
    float n4 = lse2f(D4, D5);                                                           \
    float n5 = lse3f(D5, D6, skbC ? D7 : NEGF);                                         \
    if (!(ACT1)) { n0 = g0; n1 = g1; n2 = g2; n3 = g3; n4 = hU.x; n5 = hU.y; }          \
    float E0 = lb2 + n0;             float E1 = lpS[S2][eb1] + n1;                      \
    float E2 = lb2 + n2;             float E3 = lpS[S2][eb3] + n3;                      \
    float E4 = lb2 + n4;             float E5 = lpS[S2][eb5] + n5;                      \
    float m0 = lse2f(E0, E1);                                                           \
    float m1 = lse3f(E1, E2, skbA ? E3 : NEGF);                                         \
    float m2 = lse2f(E2, E3);                                                           \
    float m3 = lse3f(E3, E4, skbB ? E5 : NEGF);                                         \
    if (ACT2) { g0 = m0; g1 = m1; g2 = m2; g3 = m3; }                                   \
    else      { g0 = n0; g1 = n1; g2 = n2; g3 = n3; }                                   \
    if (isLast) A2 = (ACT2) ? (lb2 + n4) : n4;                                          \
    halo[((J)+1)&1][tid] = make_float4(g0, g1, g2, g3);                                 \
    __syncthreads();                                                                    \
} while (0)

__global__ __launch_bounds__(NT, 1) void ctc_fb_kernel(
    const int*   __restrict__ y_true,        // (B, L)
    const float* __restrict__ y_pred,        // (B, T, C)
    const int*   __restrict__ input_length,  // (B, 1)
    const int*   __restrict__ label_length)  // (B, 1)
{
    __shared__ float  lpS[4][Cc];
    __shared__ float4 halo[2][NT + 2];

    const bool fwd = (blockIdx.x < Bc);
    const int b    = fwd ? blockIdx.x : (blockIdx.x - Bc);
    const int tid  = threadIdx.x;
    const bool isLast = (tid == NT - 1);
    const float* __restrict__ yp = y_pred + (size_t)b * Tc * Cc;
    const int*   __restrict__ yt = y_true + b * Lc;
    const int inLen  = input_length[b];
    const int labLen = label_length[b];

    if (fwd) {
        // per-thread label / skip tables for states 4t-1, 4t+1, 4t+3
        const int e1 = yt[max(2 * tid - 1, 0)];
        const int e3 = yt[2 * tid];
        const int e5 = yt[2 * tid + 1];
        const bool skp1 = (tid >= 1) && (e1 != yt[max(2 * tid - 2, 0)]);
        const bool skp3 = (tid >= 1) && (e3 != yt[max(2 * tid - 1, 0)]);
        const bool skp5 = (e5 != e3);

        float A0 = NEGF, A1 = NEGF, A2 = NEGF, A3 = NEGF, A4 = NEGF;
        if (tid == 0) {
            A0 = lg2f_(yp[BLANKc] + EPSF);
            if (labLen > 0) A1 = lg2f_(yp[yt[0]] + EPSF);
        }

        lpS[1][tid] = lg2f_(yp[(size_t)1 * Cc + tid] + EPSF);
        lpS[2][tid] = lg2f_(yp[(size_t)2 * Cc + tid] + EPSF);
        float pA0 = yp[(size_t)3 * Cc + tid], pA1 = yp[(size_t)4 * Cc + tid];
        float pB0 = yp[(size_t)5 * Cc + tid], pB1 = yp[(size_t)6 * Cc + tid];
        float pC0 = yp[(size_t)7 * Cc + tid], pC1 = yp[(size_t)8 * Cc + tid];

        halo[0][tid + 2] = make_float4(A0, A1, A2, A3);
        if (tid == 0) {
            float4 n4 = make_float4(NEGF, NEGF, NEGF, NEGF);
            halo[0][0] = n4; halo[0][1] = n4; halo[1][0] = n4; halo[1][1] = n4;
        }
        __syncthreads();

        if (inLen >= Tc) {
            for (int jj = 0; jj < 127; ++jj) {
                const int j = 2 * jj;
                FWD_BODY(j,     1, 2, 3, 0, true, true);
                FWD_BODY(j + 1, 3, 0, 1, 2, true, true);
            }
            FWD_BODY(254, 1, 2, 3, 0, true, true);
            FWD_FINAL(3, true);
        } else {
            for (int jj = 0; jj < 127; ++jj) {
                const int j = 2 * jj;
                FWD_BODY(j,     1, 2, 3, 0, (2*j+1 < inLen), (2*j+2 < inLen));
                FWD_BODY(j + 1, 3, 0, 1, 2, (2*j+3 < inLen), (2*j+4 < inLen));
            }
            FWD_BODY(254, 1, 2, 3, 0, (509 < inLen), (510 < inLen));
            FWD_FINAL(3, (511 < inLen));
        }

        float* __restrict__ aOut = g_alpha[b];
        const int sbase = 4 * tid;
        aOut[sbase] = A0; aOut[sbase + 1] = A1; aOut[sbase + 2] = A2; aOut[sbase + 3] = A3;
        if (isLast) aOut[512] = A4;

    } else {
        // per-thread labels for states 4t+1, 4t+3, 4t+5, 4t+7 (clamped)
        const int eb1 = yt[2 * tid];
        const int eb3 = yt[min(2 * tid + 1, Lc - 1)];
        const int eb5 = yt[min(2 * tid + 2, Lc - 1)];
        const int eb7 = yt[min(2 * tid + 3, Lc - 1)];
        const bool skbA = (eb3 != eb1);                       // 4t+3 <= 512 always
        const bool skbB = (tid <= 126) && (eb5 != eb3);       // target 4t+5 <= 512
        const bool skbC = (tid <= 126) && (eb7 != eb5);       // target 4t+7 <= 512

        const int se = 2 * labLen;
        const int sbase = 4 * tid;
        float g0 = (sbase     == se || (labLen > 0 && sbase     == se - 1)) ? 0.f : NEGF;
        float g1 = (sbase + 1 == se || (labLen > 0 && sbase + 1 == se - 1)) ? 0.f : NEGF;
        float g2 = (sbase + 2 == se || (labLen > 0 && sbase + 2 == se - 1)) ? 0.f : NEGF;
        float g3 = (sbase + 3 == se || (labLen > 0 && sbase + 3 == se - 1)) ? 0.f : NEGF;
        float A2 = (512 == se) ? 0.f : NEGF;   // gamma[512]

        lpS[3][tid] = lg2f_(yp[(size_t)1023 * Cc + tid] + EPSF);
        lpS[2][tid] = lg2f_(yp[(size_t)1022 * Cc + tid] + EPSF);
        float pA0 = yp[(size_t)1021 * Cc + tid], pA1 = yp[(size_t)1020 * Cc + tid];
        float pB0 = yp[(size_t)1019 * Cc + tid], pB1 = yp[(size_t)1018 * Cc + tid];
        float pC0 = yp[(size_t)1017 * Cc + tid], pC1 = yp[(size_t)1016 * Cc + tid];

        halo[0][tid] = make_float4(g0, g1, g2, g3);
        __syncthreads();

        if (inLen >= Tc) {
            for (int jj = 0; jj < 128; ++jj) {
                const int j = 2 * jj;
                BWD_BODY(j,     3, 2, 1, 0, true, true);
                BWD_BODY(j + 1, 1, 0, 3, 2, true, true);
            }
        } else {
            for (int jj = 0; jj < 128; ++jj) {
                const int j = 2 * jj;
                BWD_BODY(j,     3, 2, 1, 0, (1023-2*j < inLen), (1022-2*j < inLen));
                BWD_BODY(j + 1, 1, 0, 3, 2, (1021-2*j < inLen), (1020-2*j < inLen));
            }
        }

        float* __restrict__ gOut = g_gamma[b];
        gOut[sbase] = g0; gOut[sbase + 1] = g1; gOut[sbase + 2] = g2; gOut[sbase + 3] = g3;
        if (isLast) gOut[512] = A2;
    }
}

__global__ __launch_bounds__(128, 1) void ctc_combine_kernel(float* __restrict__ out)
{
    __shared__ float warpRes[4];
    const int b   = blockIdx.x;
    const int tid = threadIdx.x;
    const float* __restrict__ a = g_alpha[b];
    const float* __restrict__ g = g_gamma[b];

    const int s0 = tid * 4;
    float c0 = a[s0]     + g[s0];
    float c1 = a[s0 + 1] + g[s0 + 1];
    float c2 = a[s0 + 2] + g[s0 + 2];
    float c3 = a[s0 + 3] + g[s0 + 3];
    float local = lse2f(lse2f(c0, c1), lse2f(c2, c3));
    if (tid == 127) local = lse2f(local, a[512] + g[512]);
    #pragma unroll
    for (int off = 16; off > 0; off >>= 1)
        local = lse2f(local, __shfl_xor_sync(0xffffffffu, local, off));
    if ((tid & 31) == 0) warpRes[tid >> 5] = local;
    __syncthreads();
    if (tid == 0) {
        float r = lse2f(lse2f(warpRes[0], warpRes[1]), lse2f(warpRes[2], warpRes[3]));
        out[b] = -LN2F * r;
    }
}

extern "C" void kernel_launch(void* const* d_in, const int* in_sizes, int n_in,
                              void* d_out, int out_size) {
    const int*   y_true       = (const int*)d_in[0];
    const float* y_pred       = (const float*)d_in[1];
    const int*   input_length = (const int*)d_in[2];
    const int*   label_length = (const int*)d_in[3];
    float* out = (float*)d_out;

    ctc_fb_kernel<<<2 * Bc, NT>>>(y_true, y_pred, input_length, label_length);
    ctc_combine_kernel<<<Bc, 128>>>(out);
}

// round 15
// speedup vs baseline: 1.7606x; 1.0311x over previous
#include <cuda_runtime.h>
#include <cstdint>

#define NEGF (-1e30f)
#define EPSF (1e-7f)
#define LN2F (0.69314718055994531f)

constexpr int Bc = 64;
constexpr int Tc = 1024;
constexpr int Cc = 128;
constexpr int Lc = 256;
constexpr int Sc = 2 * Lc + 1;   // 513
constexpr int BLANKc = Cc - 1;   // 127
constexpr int NT = 128;

__device__ float g_alpha[Bc][Sc];
__device__ float g_gamma[Bc][Sc];

__device__ __forceinline__ float ex2f_(float x){ float r; asm("ex2.approx.ftz.f32 %0, %1;" : "=f"(r) : "f"(x)); return r; }
__device__ __forceinline__ float lg2f_(float x){ float r; asm("lg2.approx.f32 %0, %1;"    : "=f"(r) : "f"(x)); return r; }

// lse2: R10 form (both operands feed the asm directly; no hidden extra ops)
__device__ __forceinline__ float lse2f(float a, float b){
    float m = fmaxf(a, b), l = fminf(a, b);
    return m + lg2f_(1.0f + ex2f_(l - m));
}
// lse3: 4 FMNMX instead of 6 — the two non-max values are fmin(fmax(x,y),z) and
// fmin(x,y); their order in the sum is irrelevant, and max depth drops one level.
__device__ __forceinline__ float lse3f(float x, float y, float z){
    float hi = fmaxf(x, y), lo = fminf(x, y);
    float m  = fmaxf(hi, z);
    float o1 = fminf(hi, z);
    return m + lg2f_(1.0f + ex2f_(o1 - m) + ex2f_(lo - m));
}

// ---------------- forward 2-step block (states: 4*tid .. 4*tid+3, +512 on last) ----------------
#define FWD_BODY(J, S1, S2, S3, S4, ACT1, ACT2) do {                                   \
    lpS[S3][tid] = lg2f_(pA0 + EPSF);                                                   \
    lpS[S4][tid] = lg2f_(pA1 + EPSF);                                                   \
    pA0 = pB0; pA1 = pB1; pB0 = pC0; pB1 = pC1;                                         \
    pC0 = yp[(size_t)(2*(J)+ 9) * Cc + tid];                                            \
    pC1 = yp[(size_t)(2*(J)+10) * Cc + tid];                                            \
    float4 hB = halo[(J)&1][tid+1];                                                     \
    const float lb1 = lpS[S1][BLANKc], lb2 = lpS[S2][BLANKc];                           \
    float n1 = lse3f(hB.w, hB.z, skp1 ? hB.y : NEGF) + lpS[S1][e1];                     \
    float n2 = lse2f(A0, hB.w) + lb1;                                                   \
    float n3 = lse3f(A1, A0, skp3 ? hB.w : NEGF) + lpS[S1][e3];                         \
    float n4 = lse2f(A2, A1) + lb1;                                                     \
    float n5 = lse3f(A3, A2, skp5 ? A1 : NEGF) + lpS[S1][e5];                           \
    float n6 = 0.f;                                                                     \
    if (isLast) n6 = (ACT1) ? (lse2f(A4, A3) + lb1) : A4;                               \
    if (!(ACT1)) { n1 = hB.w; n2 = A0; n3 = A1; n4 = A2; n5 = A3; }                     \
    float w0 = lse2f(n2, n1) + lb2;                                                     \
    float w1 = lse3f(n3, n2, skp3 ? n1 : NEGF) + lpS[S2][e3];                           \
    float w2 = lse2f(n4, n3) + lb2;                                                     \
    float w3 = lse3f(n5, n4, skp5 ? n3 : NEGF) + lpS[S2][e5];                           \
    if (ACT2) { A0 = w0; A1 = w1; A2 = w2; A3 = w3; }                                   \
    else      { A0 = n2; A1 = n3; A2 = n4; A3 = n5; }                                   \
    if (isLast) A4 = (ACT2) ? (lse2f(n6, n5) + lb2) : n6;                               \
    halo[((J)+1)&1][tid+2] = make_float4(A0, A1, A2, A3);                               \
    __syncthreads();                                                                    \
} while (0)

#define FWD_FINAL(S, ACT) do {                                                          \
    float4 hB = halo[255 & 1][tid+1];                                                   \
    const float lbf = lpS[S][BLANKc];                                                   \
    float w0 = lse2f(A0, hB.w) + lbf;                                                   \
    float w1 = lse3f(A1, A0, skp3 ? hB.w : NEGF) + lpS[S][e3];                          \
    float w2 = lse2f(A2, A1) + lbf;                                                     \
    float w3 = lse3f(A3, A2, skp5 ? A1 : NEGF) + lpS[S][e5];                            \
    float w4 = 0.f;                                                                     \
    if (isLast) w4 = lse2f(A4, A3) + lbf;                                               \
    if (ACT) { A0 = w0; A1 = w1; A2 = w2; A3 = w3; if (isLast) A4 = w4; }               \
} while (0)

// ---------------- backward 2-step block (states: 4*tid .. 4*tid+3, +512 on last) ----------------
#define BWD_BODY(J, S1, S2, S3, S4, ACT1, ACT2) do {                                    \
    lpS[S3][tid] = lg2f_(pA0 + EPSF);                                                   \
    lpS[S4][tid] = lg2f_(pA1 + EPSF);                                                   \
    pA0 = pB0; pA1 = pB1; pB0 = pC0; pB1 = pC1;                                         \
    pC0 = yp[(size_t)(1015 - 2*(J)) * Cc + tid];                                        \
    pC1 = yp[(size_t)(1014 - 2*(J)) * Cc + tid];                                        \
    float4 hU = halo[(J)&1][tid+1];                                                     \
    if (isLast) hU = make_float4(A2, NEGF, NEGF, NEGF);                                 \
    const float lb1 = lpS[S1][BLANKc], lb2 = lpS[S2][BLANKc];                           \
    float D0 = lb1 + g0;             float D1 = lpS[S1][eb1] + g1;                      \
    float D2 = lb1 + g2;             float D3 = lpS[S1][eb3] + g3;                      \
    float D4 = lb1 + hU.x;           float D5 = lpS[S1][eb5] + hU.y;                    \
    float D6 = lb1 + hU.z;           float D7 = lpS[S1][eb7] + hU.w;                    \
    float n0 = lse2f(D0, D1);                                                           \
    float n1 = lse3f(D1, D2, skbA ? D3 : NEGF);                                         \
    float n2 = lse2f(D2, D3);                                                           \
    float n3 = lse3f(D3, D4, skbB ? D5 : NEGF);                                         \
    float n4 = lse2f(D4, D5);                                                           \
    float n5 = lse3f(D5, D6, skbC ? D7 : NEGF);                                         \
    if (!(ACT1)) { n0 = g0; n1 = g1; n2 = g2; n3 = g3; n4 = hU.x; n5 = hU.y; }          \
    float E0 = lb2 + n0;             float E1 = lpS[S2][eb1] + n1;                      \
    float E2 = lb2 + n2;             float E3 = lpS[S2][eb3] + n3;                      \
    float E4 = lb2 + n4;             float E5 = lpS[S2][eb5] + n5;                      \
    float m0 = lse2f(E0, E1);                                                           \
    float m1 = lse3f(E1, E2, skbA ? E3 : NEGF);                                         \
    float m2 = lse2f(E2, E3);                                                           \
    float m3 = lse3f(E3, E4, skbB ? E5 : NEGF);                                         \
    if (ACT2) { g0 = m0; g1 = m1; g2 = m2; g3 = m3; }                                   \
    else      { g0 = n0; g1 = n1; g2 = n2; g3 = n3; }                                   \
    if (isLast) A2 = (ACT2) ? (lb2 + n4) : n4;                                          \
    halo[((J)+1)&1][tid] = make_float4(g0, g1, g2, g3);                                 \
    __syncthreads();                                                                    \
} while (0)

__global__ __launch_bounds__(NT, 1) void ctc_fb_kernel(
    const int*   __restrict__ y_true,        // (B, L)
    const float* __restrict__ y_pred,        // (B, T, C)
    const int*   __restrict__ input_length,  // (B, 1)
    const int*   __restrict__ label_length)  // (B, 1)
{
    __shared__ float  lpS[4][Cc];
    __shared__ float4 halo[2][NT + 2];

    const bool fwd = (blockIdx.x < Bc);
    const int b    = fwd ? blockIdx.x : (blockIdx.x - Bc);
    const int tid  = threadIdx.x;
    const bool isLast = (tid == NT - 1);
    const float* __restrict__ yp = y_pred + (size_t)b * Tc * Cc;
    const int*   __restrict__ yt = y_true + b * Lc;
    const int inLen  = input_length[b];
    const int labLen = label_length[b];

    if (fwd) {
        // per-thread label / skip tables for states 4t-1, 4t+1, 4t+3
        const int e1 = yt[max(2 * tid - 1, 0)];
        const int e3 = yt[2 * tid];
        const int e5 = yt[2 * tid + 1];
        const bool skp1 = (tid >= 1) && (e1 != yt[max(2 * tid - 2, 0)]);
        const bool skp3 = (tid >= 1) && (e3 != yt[max(2 * tid - 1, 0)]);
        const bool skp5 = (e5 != e3);

        float A0 = NEGF, A1 = NEGF, A2 = NEGF, A3 = NEGF, A4 = NEGF;
        if (tid == 0) {
            A0 = lg2f_(yp[BLANKc] + EPSF);
            if (labLen > 0) A1 = lg2f_(yp[yt[0]] + EPSF);
        }

        lpS[1][tid] = lg2f_(yp[(size_t)1 * Cc + tid] + EPSF);
        lpS[2][tid] = lg2f_(yp[(size_t)2 * Cc + tid] + EPSF);
        float pA0 = yp[(size_t)3 * Cc + tid], pA1 = yp[(size_t)4 * Cc + tid];
        float pB0 = yp[(size_t)5 * Cc + tid], pB1 = yp[(size_t)6 * Cc + tid];
        float pC0 = yp[(size_t)7 * Cc + tid], pC1 = yp[(size_t)8 * Cc + tid];

        halo[0][tid + 2] = make_float4(A0, A1, A2, A3);
        if (tid == 0) {
            float4 n4 = make_float4(NEGF, NEGF, NEGF, NEGF);
            halo[0][0] = n4; halo[0][1] = n4; halo[1][0] = n4; halo[1][1] = n4;
        }
        __syncthreads();

        if (inLen >= Tc) {
            for (int jj = 0; jj < 127; ++jj) {
                const int j = 2 * jj;
                FWD_BODY(j,     1, 2, 3, 0, true, true);
                FWD_BODY(j + 1, 3, 0, 1, 2, true, true);
            }
            FWD_BODY(254, 1, 2, 3, 0, true, true);
            FWD_FINAL(3, true);
        } else {
            for (int jj = 0; jj < 127; ++jj) {
                const int j = 2 * jj;
                FWD_BODY(j,     1, 2, 3, 0, (2*j+1 < inLen), (2*j+2 < inLen));
                FWD_BODY(j + 1, 3, 0, 1, 2, (2*j+3 < inLen), (2*j+4 < inLen));
            }
            FWD_BODY(254, 1, 2, 3, 0, (509 < inLen), (510 < inLen));
            FWD_FINAL(3, (511 < inLen));
        }

        float* __restrict__ aOut = g_alpha[b];
        const int sbase = 4 * tid;
        aOut[sbase] = A0; aOut[sbase + 1] = A1; aOut[sbase + 2] = A2; aOut[sbase + 3] = A3;
        if (isLast) aOut[512] = A4;

    } else {
        // per-thread labels for states 4t+1, 4t+3, 4t+5, 4t+7 (clamped)
        const int eb1 = yt[2 * tid];
        const int eb3 = yt[min(2 * tid + 1, Lc - 1)];
        const int eb5 = yt[min(2 * tid + 2, Lc - 1)];
        const int eb7 = yt[min(2 * tid + 3, Lc - 1)];
        const bool skbA = (eb3 != eb1);                       // 4t+3 <= 512 always
        const bool skbB = (tid <= 126) && (eb5 != eb3);       // target 4t+5 <= 512
        const bool skbC = (tid <= 126) && (eb7 != eb5);       // target 4t+7 <= 512

        const int se = 2 * labLen;
        const int sbase = 4 * tid;
        float g0 = (sbase     == se || (labLen > 0 && sbase     == se - 1)) ? 0.f : NEGF;
        float g1 = (sbase + 1 == se || (labLen > 0 && sbase + 1 == se - 1)) ? 0.f : NEGF;
        float g2 = (sbase + 2 == se || (labLen > 0 && sbase + 2 == se - 1)) ? 0.f : NEGF;
        float g3 = (sbase + 3 == se || (labLen > 0 && sbase + 3 == se - 1)) ? 0.f : NEGF;
        float A2 = (512 == se) ? 0.f : NEGF;   // gamma[512]

        lpS[3][tid] = lg2f_(yp[(size_t)1023 * Cc + tid] + EPSF);
        lpS[2][tid] = lg2f_(yp[(size_t)1022 * Cc + tid] + EPSF);
        float pA0 = yp[(size_t)1021 * Cc + tid], pA1 = yp[(size_t)1020 * Cc + tid];
        float pB0 = yp[(size_t)1019 * Cc + tid], pB1 = yp[(size_t)1018 * Cc + tid];
        float pC0 = yp[(size_t)1017 * Cc + tid], pC1 = yp[(size_t)1016 * Cc + tid];

        halo[0][tid] = make_float4(g0, g1, g2, g3);
        __syncthreads();

        if (inLen >= Tc) {
            for (int jj = 0; jj < 128; ++jj) {
                const int j = 2 * jj;
                BWD_BODY(j,     3, 2, 1, 0, true, true);
                BWD_BODY(j + 1, 1, 0, 3, 2, true, true);
            }
        } else {
            for (int jj = 0; jj < 128; ++jj) {
                const int j = 2 * jj;
                BWD_BODY(j,     3, 2, 1, 0, (1023-2*j < inLen), (1022-2*j < inLen));
                BWD_BODY(j + 1, 1, 0, 3, 2, (1021-2*j < inLen), (1020-2*j < inLen));
            }
        }

        float* __restrict__ gOut = g_gamma[b];
        gOut[sbase] = g0; gOut[sbase + 1] = g1; gOut[sbase + 2] = g2; gOut[sbase + 3] = g3;
        if (isLast) gOut[512] = A2;
    }
}

__global__ __launch_bounds__(128, 1) void ctc_combine_kernel(float* __restrict__ out)
{
    __shared__ float warpRes[4];
    const int b   = blockIdx.x;
    const int tid = threadIdx.x;
    const float* __restrict__ a = g_alpha[b];
    const float* __restrict__ g = g_gamma[b];

    const int s0 = tid * 4;
    float c0 = a[s0]     + g[s0];
    float c1 = a[s0 + 1] + g[s0 + 1];
    float c2 = a[s0 + 2] + g[s0 + 2];
    float c3 = a[s0 + 3] + g[s0 + 3];
    float local = lse2f(lse2f(c0, c1), lse2f(c2, c3));
    if (tid == 127) local = lse2f(local, a[512] + g[512]);
    #pragma unroll
    for (int off = 16; off > 0; off >>= 1)
        local = lse2f(local, __shfl_xor_sync(0xffffffffu, local, off));
    if ((tid & 31) == 0) warpRes[tid >> 5] = local;
    __syncthreads();
    if (tid == 0) {
        float r = lse2f(lse2f(warpRes[0], warpRes[1]), lse2f(warpRes[2], warpRes[3]));
        out[b] = -LN2F * r;
    }
}

extern "C" void kernel_launch(void* const* d_in, const int* in_sizes, int n_in,
                              void* d_out, int out_size) {
    const int*   y_true       = (const int*)d_in[0];
    const float* y_pred       = (const float*)d_in[1];
    const int*   input_length = (const int*)d_in[2];
    const int*   label_length = (const int*)d_in[3];
    float* out = (float*)d_out;

    ctc_fb_kernel<<<2 * Bc, NT>>>(y_true, y_pred, input_length, label_length);
    ctc_combine_kernel<<<Bc, 128>>>(out);
}

// round 16
// speedup vs baseline: 1.8132x; 1.0299x over previous
#include <cuda_runtime.h>
#include <cstdint>

#define NEGF (-1e30f)
#define EPSF (1e-7f)
#define LN2F (0.69314718055994531f)

constexpr int Bc = 64;
constexpr int Tc = 1024;
constexpr int Cc = 128;
constexpr int Lc = 256;
constexpr int Sc = 2 * Lc + 1;   // 513
constexpr int BLANKc = Cc - 1;   // 127
constexpr int NT = 128;

__device__ float g_alpha[Bc][Sc];
__device__ float g_gamma[Bc][Sc];

__device__ __forceinline__ float ex2f_(float x){ float r; asm("ex2.approx.ftz.f32 %0, %1;" : "=f"(r) : "f"(x)); return r; }
__device__ __forceinline__ float lg2f_(float x){ float r; asm("lg2.approx.f32 %0, %1;"    : "=f"(r) : "f"(x)); return r; }

__device__ __forceinline__ float lse2f(float a, float b){
    float m = fmaxf(a, b), l = fminf(a, b);
    return m + lg2f_(1.0f + ex2f_(l - m));
}
__device__ __forceinline__ float lse3f(float x, float y, float z){
    float hi = fmaxf(x, y), lo = fminf(x, y);
    float m  = fmaxf(hi, z), t1 = fminf(hi, z);
    float mid = fmaxf(t1, lo), low = fminf(t1, lo);
    return m + lg2f_(1.0f + ex2f_(mid - m) + ex2f_(low - m));
}

// ---------------- forward 2-step block (states: 4*tid .. 4*tid+3, +512 on last) ----------------
#define FWD_BODY(J, S1, S2, S3, S4, ACT1, ACT2) do {                                   \
    lpS[S3][tid] = lg2f_(pA0 + EPSF);                                                   \
    lpS[S4][tid] = lg2f_(pA1 + EPSF);                                                   \
    pA0 = pB0; pA1 = pB1; pB0 = pC0; pB1 = pC1;                                         \
    pC0 = yp[(size_t)(2*(J)+ 9) * Cc + tid];                                            \
    pC1 = yp[(size_t)(2*(J)+10) * Cc + tid];                                            \
    float4 hB = halo[(J)&1][tid+1];                                                     \
    const float lb1 = lpS[S1][BLANKc], lb2 = lpS[S2][BLANKc];                           \
    float n1 = lse3f(hB.w, hB.z, skp1 ? hB.y : NEGF) + lpS[S1][e1];                     \
    float n2 = lse2f(A0, hB.w) + lb1;                                                   \
    float n3 = lse3f(A1, A0, skp3 ? hB.w : NEGF) + lpS[S1][e3];                         \
    float n4 = lse2f(A2, A1) + lb1;                                                     \
    float n5 = lse3f(A3, A2, skp5 ? A1 : NEGF) + lpS[S1][e5];                           \
    float n6 = 0.f;                                                                     \
    if (isLast) n6 = (ACT1) ? (lse2f(A4, A3) + lb1) : A4;                               \
    if (!(ACT1)) { n1 = hB.w; n2 = A0; n3 = A1; n4 = A2; n5 = A3; }                     \
    float w0 = lse2f(n2, n1) + lb2;                                                     \
    float w1 = lse3f(n3, n2, skp3 ? n1 : NEGF) + lpS[S2][e3];                           \
    float w2 = lse2f(n4, n3) + lb2;                                                     \
    float w3 = lse3f(n5, n4, skp5 ? n3 : NEGF) + lpS[S2][e5];                           \
    if (ACT2) { A0 = w0; A1 = w1; A2 = w2; A3 = w3; }                                   \
    else      { A0 = n2; A1 = n3; A2 = n4; A3 = n5; }                                   \
    if (isLast) A4 = (ACT2) ? (lse2f(n6, n5) + lb2) : n6;                               \
    halo[((J)+1)&1][tid+2] = make_float4(A0, A1, A2, A3);                               \
    __syncthreads();                                                                    \
} while (0)

#define FWD_FINAL(S, ACT) do {                                                          \
    float4 hB = halo[255 & 1][tid+1];                                                   \
    const float lbf = lpS[S][BLANKc];                                                   \
    float w0 = lse2f(A0, hB.w) + lbf;                                                   \
    float w1 = lse3f(A1, A0, skp3 ? hB.w : NEGF) + lpS[S][e3];                          \
    float w2 = lse2f(A2, A1) + lbf;                                                     \
    float w3 = lse3f(A3, A2, skp5 ? A1 : NEGF) + lpS[S][e5];                            \
    float w4 = 0.f;                                                                     \
    if (isLast) w4 = lse2f(A4, A3) + lbf;                                               \
    if (ACT) { A0 = w0; A1 = w1; A2 = w2; A3 = w3; if (isLast) A4 = w4; }               \
} while (0)

// ---------------- backward 2-step block (states: 4*tid .. 4*tid+3, +512 on last) ----------------
#define BWD_BODY(J, S1, S2, S3, S4, ACT1, ACT2) do {                                    \
    lpS[S3][tid] = lg2f_(pA0 + EPSF);                                                   \
    lpS[S4][tid] = lg2f_(pA1 + EPSF);                                                   \
    pA0 = pB0; pA1 = pB1; pB0 = pC0; pB1 = pC1;                                         \
    pC0 = yp[(size_t)(1015 - 2*(J)) * Cc + tid];                                        \
    pC1 = yp[(size_t)(1014 - 2*(J)) * Cc + tid];                                        \
    float4 hU = halo[(J)&1][tid+1];                                                     \
    if (isLast) hU = make_float4(A2, NEGF, NEGF, NEGF);                                 \
    const float lb1 = lpS[S1][BLANKc], lb2 = lpS[S2][BLANKc];                           \
    float D0 = lb1 + g0;             float D1 = lpS[S1][eb1] + g1;                      \
    float D2 = lb1 + g2;             float D3 = lpS[S1][eb3] + g3;                      \
    float D4 = lb1 + hU.x;           float D5 = lpS[S1][eb5] + hU.y;                    \
    float D6 = lb1 + hU.z;           float D7 = lpS[S1][eb7] + hU.w;                    \
    float n0 = lse2f(D0, D1);                                                           \
    float n1 = lse3f(D1, D2, skbA ? D3 : NEGF);                                         \
    float n2 = lse2f(D2, D3);                                                           \
    float n3 = lse3f(D3, D4, skbB ? D5 : NEGF);                                         \
    float n4 = lse2f(D4, D5);                                                           \
    float n5 = lse3f(D5, D6, skbC ? D7 : NEGF);                                         \
    if (!(ACT1)) { n0 = g0; n1 = g1; n2 = g2; n3 = g3; n4 = hU.x; n5 = hU.y; }          \
    float E0 = lb2 + n0;             float E1 = lpS[S2][eb1] + n1;                      \
    float E2 = lb2 + n2;             float E3 = lpS[S2][eb3] + n3;                      \
    float E4 = lb2 + n4;             float E5 = lpS[S2][eb5] + n5;                      \
    float m0 = lse2f(E0, E1);                                                           \
    float m1 = lse3f(E1, E2, skbA ? E3 : NEGF);                                         \
    float m2 = lse2f(E2, E3);                                                           \
    float m3 = lse3f(E3, E4, skbB ? E5 : NEGF);                                         \
    if (ACT2) { g0 = m0; g1 = m1; g2 = m2; g3 = m3; }                                   \
    else      { g0 = n0; g1 = n1; g2 = n2; g3 = n3; }                                   \
    if (isLast) A2 = (ACT2) ? (lb2 + n4) : n4;                                          \
    halo[((J)+1)&1][tid] = make_float4(g0, g1, g2, g3);                                 \
    __syncthreads();                                                                    \
} while (0)

__global__ __launch_bounds__(NT, 1) void ctc_fb_kernel(
    const int*   __restrict__ y_true,        // (B, L)
    const float* __restrict__ y_pred,        // (B, T, C)
    const int*   __restrict__ input_length,  // (B, 1)
    const int*   __restrict__ label_length)  // (B, 1)
{
    __shared__ float  lpS[4][Cc];
    __shared__ float4 halo[2][NT + 2];

    const bool fwd = (blockIdx.x < Bc);
    const int b    = fwd ? blockIdx.x : (blockIdx.x - Bc);
    const int tid  = threadIdx.x;
    const bool isLast = (tid == NT - 1);
    const float* __restrict__ yp = y_pred + (size_t)b * Tc * Cc;
    const int*   __restrict__ yt = y_true + b * Lc;
    const int inLen  = input_length[b];
    const int labLen = label_length[b];

    if (fwd) {
        // per-thread label / skip tables for states 4t-1, 4t+1, 4t+3
        const int e1 = yt[max(2 * tid - 1, 0)];
        const int e3 = yt[2 * tid];
        const int e5 = yt[2 * tid + 1];
        const bool skp1 = (tid >= 1) && (e1 != yt[max(2 * tid - 2, 0)]);
        const bool skp3 = (tid >= 1) && (e3 != yt[max(2 * tid - 1, 0)]);
        const bool skp5 = (e5 != e3);

        float A0 = NEGF, A1 = NEGF, A2 = NEGF, A3 = NEGF, A4 = NEGF;
        if (tid == 0) {
            A0 = lg2f_(yp[BLANKc] + EPSF);
            if (labLen > 0) A1 = lg2f_(yp[yt[0]] + EPSF);
        }

        lpS[1][tid] = lg2f_(yp[(size_t)1 * Cc + tid] + EPSF);
        lpS[2][tid] = lg2f_(yp[(size_t)2 * Cc + tid] + EPSF);
        float pA0 = yp[(size_t)3 * Cc + tid], pA1 = yp[(size_t)4 * Cc + tid];
        float pB0 = yp[(size_t)5 * Cc + tid], pB1 = yp[(size_t)6 * Cc + tid];
        float pC0 = yp[(size_t)7 * Cc + tid], pC1 = yp[(size_t)8 * Cc + tid];

        halo[0][tid + 2] = make_float4(A0, A1, A2, A3);
        if (tid == 0) {
            float4 n4 = make_float4(NEGF, NEGF, NEGF, NEGF);
            halo[0][0] = n4; halo[0][1] = n4; halo[1][0] = n4; halo[1][1] = n4;
        }
        __syncthreads();

        if (inLen >= Tc) {
            for (int jj = 0; jj < 127; ++jj) {
                const int j = 2 * jj;
                FWD_BODY(j,     1, 2, 3, 0, true, true);
                FWD_BODY(j + 1, 3, 0, 1, 2, true, true);
            }
            FWD_BODY(254, 1, 2, 3, 0, true, true);
            FWD_FINAL(3, true);
        } else {
            for (int jj = 0; jj < 127; ++jj) {
                const int j = 2 * jj;
                FWD_BODY(j,     1, 2, 3, 0, (2*j+1 < inLen), (2*j+2 < inLen));
                FWD_BODY(j + 1, 3, 0, 1, 2, (2*j+3 < inLen), (2*j+4 < inLen));
            }
            FWD_BODY(254, 1, 2, 3, 0, (509 < inLen), (510 < inLen));
            FWD_FINAL(3, (511 < inLen));
        }

        float* __restrict__ aOut = g_alpha[b];
        const int sbase = 4 * tid;
        aOut[sbase] = A0; aOut[sbase + 1] = A1; aOut[sbase + 2] = A2; aOut[sbase + 3] = A3;
        if (isLast) aOut[512] = A4;

    } else {
        // per-thread labels for states 4t+1, 4t+3, 4t+5, 4t+7 (clamped)
        const int eb1 = yt[2 * tid];
        const int eb3 = yt[min(2 * tid + 1, Lc - 1)];
        const int eb5 = yt[min(2 * tid + 2, Lc - 1)];
        const int eb7 = yt[min(2 * tid + 3, Lc - 1)];
        const bool skbA = (eb3 != eb1);                       // 4t+3 <= 512 always
        const bool skbB = (tid <= 126) && (eb5 != eb3);       // target 4t+5 <= 512
        const bool skbC = (tid <= 126) && (eb7 != eb5);       // target 4t+7 <= 512

        const int se = 2 * labLen;
        const int sbase = 4 * tid;
        float g0 = (sbase     == se || (labLen > 0 && sbase     == se - 1)) ? 0.f : NEGF;
        float g1 = (sbase + 1 == se || (labLen > 0 && sbase + 1 == se - 1)) ? 0.f : NEGF;
        float g2 = (sbase + 2 == se || (labLen > 0 && sbase + 2 == se - 1)) ? 0.f : NEGF;
        float g3 = (sbase + 3 == se || (labLen > 0 && sbase + 3 == se - 1)) ? 0.f : NEGF;
        float A2 = (512 == se) ? 0.f : NEGF;   // gamma[512]

        lpS[3][tid] = lg2f_(yp[(size_t)1023 * Cc + tid] + EPSF);
        lpS[2][tid] = lg2f_(yp[(size_t)1022 * Cc + tid] + EPSF);
        float pA0 = yp[(size_t)1021 * Cc + tid], pA1 = yp[(size_t)1020 * Cc + tid];
        float pB0 = yp[(size_t)1019 * Cc + tid], pB1 = yp[(size_t)1018 * Cc + tid];
        float pC0 = yp[(size_t)1017 * Cc + tid], pC1 = yp[(size_t)1016 * Cc + tid];

        halo[0][tid] = make_float4(g0, g1, g2, g3);
        __syncthreads();

        if (inLen >= Tc) {
            for (int jj = 0; jj < 128; ++jj) {
                const int j = 2 * jj;
                BWD_BODY(j,     3, 2, 1, 0, true, true);
                BWD_BODY(j + 1, 1, 0, 3, 2, true, true);
            }
        } else {
            for (int jj = 0; jj < 128; ++jj) {
                const int j = 2 * jj;
                BWD_BODY(j,     3, 2, 1, 0, (1023-2*j < inLen), (1022-2*j < inLen));
                BWD_BODY(j + 1, 1, 0, 3, 2, (1021-2*j < inLen), (1020-2*j < inLen));
            }
        }

        float* __restrict__ gOut = g_gamma[b];
        gOut[sbase] = g0; gOut[sbase + 1] = g1; gOut[sbase + 2] = g2; gOut[sbase + 3] = g3;
        if (isLast) gOut[512] = A2;
    }
}

__global__ __launch_bounds__(128, 1) void ctc_combine_kernel(float* __restrict__ out)
{
    __shared__ float warpRes[4];
    const int b   = blockIdx.x;
    const int tid = threadIdx.x;
    const float* __restrict__ a = g_alpha[b];
    const float* __restrict__ g = g_gamma[b];

    const int s0 = tid * 4;
    float c0 = a[s0]     + g[s0];
    float c1 = a[s0 + 1] + g[s0 + 1];
    float c2 = a[s0 + 2] + g[s0 + 2];
    float c3 = a[s0 + 3] + g[s0 + 3];
    float local = lse2f(lse2f(c0, c1), lse2f(c2, c3));
    if (tid == 127) local = lse2f(local, a[512] + g[512]);
    #pragma unroll
    for (int off = 16; off > 0; off >>= 1)
        local = lse2f(local, __shfl_xor_sync(0xffffffffu, local, off));
    if ((tid & 31) == 0) warpRes[tid >> 5] = local;
    __syncthreads();
    if (tid == 0) {
        float r = lse2f(lse2f(warpRes[0], warpRes[1]), lse2f(warpRes[2], warpRes[3]));
        out[b] = -LN2F * r;
    }
}

extern "C" void kernel_launch(void* const* d_in, const int* in_sizes, int n_in,
                              void* d_out, int out_size) {
    const int*   y_true       = (const int*)d_in[0];
    const float* y_pred       = (const float*)d_in[1];
    const int*   input_length = (const int*)d_in[2];
    const int*   label_length = (const int*)d_in[3];
    float* out = (float*)d_out;

    ctc_fb_kernel<<<2 * Bc, NT>>>(y_true, y_pred, input_length, label_length);
    ctc_combine_kernel<<<Bc, 128>>>(out);
}

// round 17
// speedup vs baseline: 1.8152x; 1.0011x over previous
#include <cuda_runtime.h>
#include <cstdint>

#define NEGF (-1e30f)
#define EPSF (1e-7f)
#define LN2F (0.69314718055994531f)

constexpr int Bc = 64;
constexpr int Tc = 1024;
constexpr int Cc = 128;
constexpr int Lc = 256;
constexpr int Sc = 2 * Lc + 1;   // 513
constexpr int BLANKc = Cc - 1;   // 127
constexpr int NT = 128;

__device__ float g_alpha[Bc][Sc];
__device__ float g_gamma[Bc][Sc];

__device__ __forceinline__ float ex2f_(float x){ float r; asm("ex2.approx.ftz.f32 %0, %1;" : "=f"(r) : "f"(x)); return r; }
__device__ __forceinline__ float lg2f_(float x){ float r; asm("lg2.approx.f32 %0, %1;"    : "=f"(r) : "f"(x)); return r; }

__device__ __forceinline__ float lse2f(float a, float b){
    float m = fmaxf(a, b), l = fminf(a, b);
    return m + lg2f_(1.0f + ex2f_(l - m));
}
__device__ __forceinline__ float lse3f(float x, float y, float z){
    float hi = fmaxf(x, y), lo = fminf(x, y);
    float m  = fmaxf(hi, z), t1 = fminf(hi, z);
    float mid = fmaxf(t1, lo), low = fminf(t1, lo);
    return m + lg2f_(1.0f + ex2f_(mid - m) + ex2f_(low - m));
}

// ---------------- forward 2-step block (states: 4*tid .. 4*tid+3, +512 on last) ----------------
#define FWD_BODY(J, S1, S2, S3, S4, ACT1, ACT2) do {                                   \
    lpS[S3][tid] = lg2f_(pA0 + EPSF);                                                   \
    lpS[S4][tid] = lg2f_(pA1 + EPSF);                                                   \
    pA0 = pB0; pA1 = pB1; pB0 = pC0; pB1 = pC1;                                         \
    pC0 = yp[(size_t)(2*(J)+ 9) * Cc + tid];                                            \
    pC1 = yp[(size_t)(2*(J)+10) * Cc + tid];                                            \
    float4 hB = halo[(J)&1][tid+1];                                                     \
    const float lb1 = lpS[S1][BLANKc], lb2 = lpS[S2][BLANKc];                           \
    float n1 = lse3f(hB.w, hB.z, skp1 ? hB.y : NEGF) + lpS[S1][e1];                     \
    float n2 = lse2f(A0, hB.w) + lb1;                                                   \
    float n3 = lse3f(A1, A0, skp3 ? hB.w : NEGF) + lpS[S1][e3];                         \
    float n4 = lse2f(A2, A1) + lb1;                                                     \
    float n5 = lse3f(A3, A2, skp5 ? A1 : NEGF) + lpS[S1][e5];                           \
    float n6 = 0.f;                                                                     \
    if (isLast) n6 = (ACT1) ? (lse2f(A4, A3) + lb1) : A4;                               \
    if (!(ACT1)) { n1 = hB.w; n2 = A0; n3 = A1; n4 = A2; n5 = A3; }                     \
    float w0 = lse2f(n2, n1) + lb2;                                                     \
    float w1 = lse3f(n3, n2, skp3 ? n1 : NEGF) + lpS[S2][e3];                           \
    float w2 = lse2f(n4, n3) + lb2;                                                     \
    float w3 = lse3f(n5, n4, skp5 ? n3 : NEGF) + lpS[S2][e5];                           \
    if (ACT2) { A0 = w0; A1 = w1; A2 = w2; A3 = w3; }                                   \
    else      { A0 = n2; A1 = n3; A2 = n4; A3 = n5; }                                   \
    if (isLast) A4 = (ACT2) ? (lse2f(n6, n5) + lb2) : n6;                               \
    halo[((J)+1)&1][tid+2] = make_float4(A0, A1, A2, A3);                               \
    __syncthreads();                                                                    \
} while (0)

#define FWD_FINAL(S, ACT) do {                                                          \
    float4 hB = halo[255 & 1][tid+1];                                                   \
    const float lbf = lpS[S][BLANKc];                                                   \
    float w0 = lse2f(A0, hB.w) + lbf;                                                   \
    float w1 = lse3f(A1, A0, skp3 ? hB.w : NEGF) + lpS[S][e3];                          \
    float w2 = lse2f(A2, A1) + lbf;                                                     \
    float w3 = lse3f(A3, A2, skp5 ? A1 : NEGF) + lpS[S][e5];                            \
    float w4 = 0.f;                                                                     \
    if (isLast) w4 = lse2f(A4, A3) + lbf;                                               \
    if (ACT) { A0 = w0; A1 = w1; A2 = w2; A3 = w3; if (isLast) A4 = w4; }               \
} while (0)

// ---------------- backward 2-step block (states: 4*tid .. 4*tid+3, +512 on last) ----------------
#define BWD_BODY(J, S1, S2, S3, S4, ACT1, ACT2) do {                                    \
    lpS[S3][tid] = lg2f_(pA0 + EPSF);                                                   \
    lpS[S4][tid] = lg2f_(pA1 + EPSF);                                                   \
    pA0 = pB0; pA1 = pB1; pB0 = pC0; pB1 = pC1;                                         \
    pC0 = yp[(size_t)(1015 - 2*(J)) * Cc + tid];                                        \
    pC1 = yp[(size_t)(1014 - 2*(J)) * Cc + tid];                                        \
    float4 hU = halo[(J)&1][tid+1];                                                     \
    if (isLast) hU = make_float4(A2, NEGF, NEGF, NEGF);                                 \
    const float lb1 = lpS[S1][BLANKc], lb2 = lpS[S2][BLANKc];                           \
    float D0 = lb1 + g0;             float D1 = lpS[S1][eb1] + g1;                      \
    float D2 = lb1 + g2;             float D3 = lpS[S1][eb3] + g3;                      \
    float D4 = lb1 + hU.x;           float D5 = lpS[S1][eb5] + hU.y;                    \
    float D6 = lb1 + hU.z;           float D7 = lpS[S1][eb7] + hU.w;                    \
    float n0 = lse2f(D0, D1);                                                           \
    float n1 = lse3f(D1, D2, skbA ? D3 : NEGF);                                         \
    float n2 = lse2f(D2, D3);                                                           \
    float n3 = lse3f(D3, D4, skbB ? D5 : NEGF);                                         \
    float n4 = lse2f(D4, D5);                                                           \
    float n5 = lse3f(D5, D6, skbC ? D7 : NEGF);                                         \
    if (!(ACT1)) { n0 = g0; n1 = g1; n2 = g2; n3 = g3; n4 = hU.x; n5 = hU.y; }          \
    float E0 = lb2 + n0;             float E1 = lpS[S2][eb1] + n1;                      \
    float E2 = lb2 + n2;             float E3 = lpS[S2][eb3] + n3;                      \
    float E4 = lb2 + n4;             float E5 = lpS[S2][eb5] + n5;                      \
    float m0 = lse2f(E0, E1);                                                           \
    float m1 = lse3f(E1, E2, skbA ? E3 : NEGF);                                         \
    float m2 = lse2f(E2, E3);                                                           \
    float m3 = lse3f(E3, E4, skbB ? E5 : NEGF);                                         \
    if (ACT2) { g0 = m0; g1 = m1; g2 = m2; g3 = m3; }                                   \
    else      { g0 = n0; g1 = n1; g2 = n2; g3 = n3; }                                   \
    if (isLast) A2 = (ACT2) ? (lb2 + n4) : n4;                                          \
    halo[((J)+1)&1][tid] = make_float4(g0, g1, g2, g3);                                 \
    __syncthreads();                                                                    \
} while (0)

__global__ __launch_bounds__(NT, 1) void ctc_fb_kernel(
    const int*   __restrict__ y_true,        // (B, L)
    const float* __restrict__ y_pred,        // (B, T, C)
    const int*   __restrict__ input_length,  // (B, 1)
    const int*   __restrict__ label_length)  // (B, 1)
{
    __shared__ float  lpS[4][Cc];
    __shared__ float4 halo[2][NT + 2];

    const bool fwd = (blockIdx.x < Bc);
    const int b    = fwd ? blockIdx.x : (blockIdx.x - Bc);
    const int tid  = threadIdx.x;
    const bool isLast = (tid == NT - 1);
    const float* __restrict__ yp = y_pred + (size_t)b * Tc * Cc;
    const int*   __restrict__ yt = y_true + b * Lc;
    const int inLen  = input_length[b];
    const int labLen = label_length[b];

    if (fwd) {
        // per-thread label / skip tables for states 4t-1, 4t+1, 4t+3
        const int e1 = yt[max(2 * tid - 1, 0)];
        const int e3 = yt[2 * tid];
        const int e5 = yt[2 * tid + 1];
        const bool skp1 = (tid >= 1) && (e1 != yt[max(2 * tid - 2, 0)]);
        const bool skp3 = (tid >= 1) && (e3 != yt[max(2 * tid - 1, 0)]);
        const bool skp5 = (e5 != e3);

        float A0 = NEGF, A1 = NEGF, A2 = NEGF, A3 = NEGF, A4 = NEGF;
        if (tid == 0) {
            A0 = lg2f_(yp[BLANKc] + EPSF);
            if (labLen > 0) A1 = lg2f_(yp[yt[0]] + EPSF);
        }

        lpS[1][tid] = lg2f_(yp[(size_t)1 * Cc + tid] + EPSF);
        lpS[2][tid] = lg2f_(yp[(size_t)2 * Cc + tid] + EPSF);
        float pA0 = yp[(size_t)3 * Cc + tid], pA1 = yp[(size_t)4 * Cc + tid];
        float pB0 = yp[(size_t)5 * Cc + tid], pB1 = yp[(size_t)6 * Cc + tid];
        float pC0 = yp[(size_t)7 * Cc + tid], pC1 = yp[(size_t)8 * Cc + tid];

        halo[0][tid + 2] = make_float4(A0, A1, A2, A3);
        if (tid == 0) {
            float4 n4 = make_float4(NEGF, NEGF, NEGF, NEGF);
            halo[0][0] = n4; halo[0][1] = n4; halo[1][0] = n4; halo[1][1] = n4;
        }
        __syncthreads();

        if (inLen >= Tc) {
            for (int jj = 0; jj < 127; ++jj) {
                const int j = 2 * jj;
                FWD_BODY(j,     1, 2, 3, 0, true, true);
                FWD_BODY(j + 1, 3, 0, 1, 2, true, true);
            }
            FWD_BODY(254, 1, 2, 3, 0, true, true);
            FWD_FINAL(3, true);
        } else {
            for (int jj = 0; jj < 127; ++jj) {
                const int j = 2 * jj;
                FWD_BODY(j,     1, 2, 3, 0, (2*j+1 < inLen), (2*j+2 < inLen));
                FWD_BODY(j + 1, 3, 0, 1, 2, (2*j+3 < inLen), (2*j+4 < inLen));
            }
            FWD_BODY(254, 1, 2, 3, 0, (509 < inLen), (510 < inLen));
            FWD_FINAL(3, (511 < inLen));
        }

        float* __restrict__ aOut = g_alpha[b];
        const int sbase = 4 * tid;
        aOut[sbase] = A0; aOut[sbase + 1] = A1; aOut[sbase + 2] = A2; aOut[sbase + 3] = A3;
        if (isLast) aOut[512] = A4;

    } else {
        // per-thread labels for states 4t+1, 4t+3, 4t+5, 4t+7 (clamped)
        const int eb1 = yt[2 * tid];
        const int eb3 = yt[min(2 * tid + 1, Lc - 1)];
        const int eb5 = yt[min(2 * tid + 2, Lc - 1)];
        const int eb7 = yt[min(2 * tid + 3, Lc - 1)];
        const bool skbA = (eb3 != eb1);                       // 4t+3 <= 512 always
        const bool skbB = (tid <= 126) && (eb5 != eb3);       // target 4t+5 <= 512
        const bool skbC = (tid <= 126) && (eb7 != eb5);       // target 4t+7 <= 512

        const int se = 2 * labLen;
        const int sbase = 4 * tid;
        float g0 = (sbase     == se || (labLen > 0 && sbase     == se - 1)) ? 0.f : NEGF;
        float g1 = (sbase + 1 == se || (labLen > 0 && sbase + 1 == se - 1)) ? 0.f : NEGF;
        float g2 = (sbase + 2 == se || (labLen > 0 && sbase + 2 == se - 1)) ? 0.f : NEGF;
        float g3 = (sbase + 3 == se || (labLen > 0 && sbase + 3 == se - 1)) ? 0.f : NEGF;
        float A2 = (512 == se) ? 0.f : NEGF;   // gamma[512]

        lpS[3][tid] = lg2f_(yp[(size_t)1023 * Cc + tid] + EPSF);
        lpS[2][tid] = lg2f_(yp[(size_t)1022 * Cc + tid] + EPSF);
        float pA0 = yp[(size_t)1021 * Cc + tid], pA1 = yp[(size_t)1020 * Cc + tid];
        float pB0 = yp[(size_t)1019 * Cc + tid], pB1 = yp[(size_t)1018 * Cc + tid];
        float pC0 = yp[(size_t)1017 * Cc + tid], pC1 = yp[(size_t)1016 * Cc + tid];

        halo[0][tid] = make_float4(g0, g1, g2, g3);
        __syncthreads();

        if (inLen >= Tc) {
            for (int jj = 0; jj < 128; ++jj) {
                const int j = 2 * jj;
                BWD_BODY(j,     3, 2, 1, 0, true, true);
                BWD_BODY(j + 1, 1, 0, 3, 2, true, true);
            }
        } else {
            for (int jj = 0; jj < 128; ++jj) {
                const int j = 2 * jj;
                BWD_BODY(j,     3, 2, 1, 0, (1023-2*j < inLen), (1022-2*j < inLen));
                BWD_BODY(j + 1, 1, 0, 3, 2, (1021-2*j < inLen), (1020-2*j < inLen));
            }
        }

        float* __restrict__ gOut = g_gamma[b];
        gOut[sbase] = g0; gOut[sbase + 1] = g1; gOut[sbase + 2] = g2; gOut[sbase + 3] = g3;
        if (isLast) gOut[512] = A2;
    }
}

__global__ __launch_bounds__(128, 1) void ctc_combine_kernel(float* __restrict__ out)
{
    // PDL: CTAs launch/setup while ctc_fb_kernel drains; wait for its completion here.
    cudaGridDependencySynchronize();

    __shared__ float warpRes[4];
    const int b   = blockIdx.x;
    const int tid = threadIdx.x;
    const float* __restrict__ a = g_alpha[b];
    const float* __restrict__ g = g_gamma[b];

    const int s0 = tid * 4;
    float c0 = a[s0]     + g[s0];
    float c1 = a[s0 + 1] + g[s0 + 1];
    float c2 = a[s0 + 2] + g[s0 + 2];
    float c3 = a[s0 + 3] + g[s0 + 3];
    float local = lse2f(lse2f(c0, c1), lse2f(c2, c3));
    if (tid == 127) local = lse2f(local, a[512] + g[512]);
    #pragma unroll
    for (int off = 16; off > 0; off >>= 1)
        local = lse2f(local, __shfl_xor_sync(0xffffffffu, local, off));
    if ((tid & 31) == 0) warpRes[tid >> 5] = local;
    __syncthreads();
    if (tid == 0) {
        float r = lse2f(lse2f(warpRes[0], warpRes[1]), lse2f(warpRes[2], warpRes[3]));
        out[b] = -LN2F * r;
    }
}

extern "C" void kernel_launch(void* const* d_in, const int* in_sizes, int n_in,
                              void* d_out, int out_size) {
    const int*   y_true       = (const int*)d_in[0];
    const float* y_pred       = (const float*)d_in[1];
    const int*   input_length = (const int*)d_in[2];
    const int*   label_length = (const int*)d_in[3];
    float* out = (float*)d_out;

    ctc_fb_kernel<<<2 * Bc, NT>>>(y_true, y_pred, input_length, label_length);

    // Programmatic dependent launch: overlap combine's launch latency with fb's tail.
    cudaLaunchConfig_t cfg = {};
    cfg.gridDim  = dim3(Bc);
    cfg.blockDim = dim3(128);
    cudaLaunchAttribute attrs[1];
    attrs[0].id = cudaLaunchAttributeProgrammaticStreamSerialization;
    attrs[0].val.programmaticStreamSerializationAllowed = 1;
    cfg.attrs = attrs;
    cfg.numAttrs = 1;
    cudaLaunchKernelEx(&cfg, ctc_combine_kernel, out);
}